// round 6
// baseline (speedup 1.0000x reference)
#include <cuda_runtime.h>

// ---------------------------------------------------------------------------
// DILATE loss. B=128, T=256, D=64, gamma=0.01, alpha=0.5, eps=1e-8, BIG=1e10.
// Wavefront kernels: warp-band register wavefront. Lane l of warp w owns row
// 32w+l; all recurrence values travel via registers + 1 shuffle/step; warp
// boundaries via 64-deep smem rings with 13-step slack; __syncthreads only
// every 8 steps (bounds warp skew). 8-deep register rings prefetch the
// diagonal-major D/R streams (coalesced 128B per warp per step).
// ---------------------------------------------------------------------------

#define BATCH 128
#define TLEN  256
#define NDIAG 511              // 2*TLEN - 1
#define BIGV  1e10f
#define QNEG  -1e30f
// exp(x/gamma) = exp2(x * KE2);  KE2 = (1/gamma)*log2(e)
#define KE2   144.26950408889634f
// gamma * ln(2)
#define KL    0.006931471805599453f
#define SKEW  48               // warp start stagger (must be mult of 8)
#define SMAX  624              // 7*SKEW + 287, rounded to mult of 8

__device__ float g_D[(size_t)BATCH * NDIAG * TLEN];
__device__ float g_R[(size_t)BATCH * NDIAG * TLEN];
__device__ float g_shape[BATCH];
__device__ float g_num[BATCH];
__device__ float g_den[BATCH];

__device__ __forceinline__ float ex2f_(float x) {
    float y; asm("ex2.approx.ftz.f32 %0, %1;" : "=f"(y) : "f"(x)); return y;
}
__device__ __forceinline__ float lg2f_(float x) {
    float y; asm("lg2.approx.ftz.f32 %0, %1;" : "=f"(y) : "f"(x)); return y;
}
__device__ __forceinline__ float softmin3(float z0, float z1, float z2) {
    float m = fminf(z0, fminf(z1, z2));
    float s = ex2f_((m - z0) * KE2) + ex2f_((m - z1) * KE2)
            + ex2f_((m - z2) * KE2);
    return m - KL * lg2f_(s);
}

// ---------------------------------------------------------------------------
// Kernel 1: pairwise squared distances in diagonal layout (float4 smem).
// ---------------------------------------------------------------------------
__global__ __launch_bounds__(256) void dist_kernel(
    const float* __restrict__ preds, const float* __restrict__ targets)
{
    __shared__ float pool[2 * 64 * 68 + 128];
    float*  ps  = pool;                   // [64][68]
    float*  ts  = pool + 64 * 68;
    float*  pn  = pool + 2 * 64 * 68;     // [64]
    float*  tn  = pn + 64;
    float4* ps4 = (float4*)ps;            // pitch 17
    float4* ts4 = (float4*)ts;

    const int b  = blockIdx.z;
    const int i0 = blockIdx.y * 64;
    const int j0 = blockIdx.x * 64;
    const int tid = threadIdx.x;

    const float4* pb4 = (const float4*)(preds   + (size_t)b * TLEN * 64 + (size_t)i0 * 64);
    const float4* tb4 = (const float4*)(targets + (size_t)b * TLEN * 64 + (size_t)j0 * 64);

#pragma unroll
    for (int q = 0; q < 4; q++) {
        int idx = q * 256 + tid;          // 0..1023 float4s
        int r = idx >> 4, c4 = idx & 15;
        ps4[r * 17 + c4] = pb4[idx];
        ts4[r * 17 + c4] = tb4[idx];
    }
    __syncthreads();

    if (tid < 128) {
        const float* src = (tid < 64) ? ps : ts;
        float* dst = (tid < 64) ? pn : tn;
        int r = tid & 63;
        float s = 0.0f;
#pragma unroll
        for (int k = 0; k < 64; k++) { float v = src[r * 68 + k]; s = fmaf(v, v, s); }
        dst[r] = s;
    }
    __syncthreads();

    const int tx = tid & 15, ty = tid >> 4;
    const int ib = ty * 4, jb = tx * 4;

    float acc[4][4];
#pragma unroll
    for (int r = 0; r < 4; r++)
#pragma unroll
        for (int c = 0; c < 4; c++) acc[r][c] = 0.0f;

#pragma unroll 4
    for (int kq = 0; kq < 16; kq++) {
        float4 pv[4], tv[4];
#pragma unroll
        for (int r = 0; r < 4; r++) pv[r] = ps4[(ib + r) * 17 + kq];
#pragma unroll
        for (int c = 0; c < 4; c++) tv[c] = ts4[(jb + c) * 17 + kq];
#pragma unroll
        for (int r = 0; r < 4; r++)
#pragma unroll
            for (int c = 0; c < 4; c++) {
                acc[r][c] = fmaf(pv[r].x, tv[c].x, acc[r][c]);
                acc[r][c] = fmaf(pv[r].y, tv[c].y, acc[r][c]);
                acc[r][c] = fmaf(pv[r].z, tv[c].z, acc[r][c]);
                acc[r][c] = fmaf(pv[r].w, tv[c].w, acc[r][c]);
            }
    }

    float pnr[4], tnr[4];
#pragma unroll
    for (int r = 0; r < 4; r++) pnr[r] = pn[ib + r];
#pragma unroll
    for (int c = 0; c < 4; c++) tnr[c] = tn[jb + c];

    __syncthreads();

    // Stage tile diagonally: buf[tdd][ii], tdd = local i+j (0..126), pitch 65.
    float* buf = pool;
#pragma unroll
    for (int r = 0; r < 4; r++)
#pragma unroll
        for (int c = 0; c < 4; c++) {
            int ii = ib + r, jj = jb + c;
            float dv = pnr[r] + tnr[c] - 2.0f * acc[r][c];
            buf[(ii + jj) * 65 + ii] = fmaxf(dv, 0.0f);
        }
    __syncthreads();

    for (int base = 0; base < 128; base += 4) {
        int tdd = base + (tid >> 6);
        int ii  = tid & 63;
        if (tdd < 127) {
            int jj = tdd - ii;
            if (jj >= 0 && jj < 64)
                g_D[((size_t)b * NDIAG + (i0 + j0 + tdd)) * TLEN + (i0 + ii)]
                    = buf[tdd * 65 + ii];
        }
    }
}

// ---------------------------------------------------------------------------
// Kernel 2: soft-DTW forward, warp-band register wavefront.
// Lane l of warp w = row i = 32w+l. Warp w starts at global step 48w.
// At local step t: cell (i, j = t - l), diag d = 32w + t.
// ---------------------------------------------------------------------------
__global__ __launch_bounds__(256) void fwd_kernel()
{
    __shared__ float bnd[8][64];   // bnd[w][j&63] = R(32w+31, j)

    const int b   = blockIdx.x;
    const int tid = threadIdx.x;
    const int w   = tid >> 5, l = tid & 31;
    const int i   = tid;
    const int Gw  = w * SKEW;

    const float* Dp = g_D + (size_t)b * NDIAG * TLEN + i;
    float*       Rp = g_R + (size_t)b * NDIAG * TLEN + i;
    const int rowbase = w << 5;    // d = rowbase + t

    float ringD[8];
#pragma unroll
    for (int k = 0; k < 8; k++) ringD[k] = Dp[(size_t)(rowbase + k) * TLEN];

    float pfB[4];
    float Rown = BIGV, Rdiag = BIGV, Rprev = BIGV, Rres = BIGV;

    int t = -Gw;
    for (int s8 = 0; s8 < SMAX; s8 += 8) {
#pragma unroll
        for (int k = 0; k < 8; k++) {
            // 1. neighbor above via shuffle (lane 0: boundary ring consume)
            float Rup = __shfl_up_sync(0xFFFFFFFFu, Rprev, 1);
            if (l == 0) {
                float bv = pfB[(s8 + k) & 3];
                Rup = (w > 0 && (unsigned)t <= 255u) ? bv : BIGV;
            }
            // 2. boundary prefetch 4 ahead (consumed 4 steps later, same slot)
            if (l == 0 && w > 0 && (unsigned)(t + 4) <= 255u)
                pfB[(s8 + k) & 3] = ((volatile float*)bnd[w - 1])[(t + 4) & 63];
            // 3. compute
            if ((unsigned)(t - l) <= 255u) {
                float Dv = ringD[(s8 + k) & 7];
                float R;
                if (i == 0 && t == 0) R = Dv;               // cell (0,0)
                else R = Dv + softmin3(Rdiag, Rup, Rown);
                Rp[(size_t)(rowbase + t) * TLEN] = R;
                if (l == 31)
                    ((volatile float*)bnd[w])[(t - 31) & 63] = R;
                Rdiag = Rup; Rown = R; Rprev = R; Rres = R;
            }
            // 4. refill D ring (slot just consumed)
            if ((unsigned)(t + 8) <= 286u)
                ringD[(s8 + k) & 7] = Dp[(size_t)(rowbase + t + 8) * TLEN];
            t++;
        }
        __syncthreads();
    }

    if (i == 255) g_shape[b] = Rres;   // R[255,255]
}

// ---------------------------------------------------------------------------
// Kernel 3: soft-DTW gradient, reverse warp-band wavefront.
// Lane l of warp w = row i = 32w+l, sweeping j downward. Warp 7 starts first.
// At local step t: j = 286 - t - l, diag d = 32w + 286 - t.
// E(i,j) = E(i+1,j)*ex2(Q(i+1,j)-t) + E(i,j+1)*ex2(Q(i,j+1)-t)
//        + E(i+1,j+1)*ex2(Q(i+1,j+1)-t),  t = R(i,j)*KE2, Q = (R-D)*KE2.
// ---------------------------------------------------------------------------
__global__ __launch_bounds__(256) void bwd_kernel()
{
    __shared__ float bndE[8][64];  // (E,Q)(32w, j) written by lane 0 of warp w
    __shared__ float bndQ[8][64];
    __shared__ float red[16];

    const int b   = blockIdx.x;
    const int tid = threadIdx.x;
    const int w   = tid >> 5, l = tid & 31;
    const int i   = tid;
    const int Gw  = (7 - w) * SKEW;

    const float* Rp = g_R + (size_t)b * NDIAG * TLEN + i;
    const float* Dp = g_D + (size_t)b * NDIAG * TLEN + i;
    const int rowtop = (w << 5) + 286;   // d = rowtop - t

    float ringR[8], ringD[8];
#pragma unroll
    for (int k = 0; k < 8; k++) {
        size_t off = (size_t)(rowtop - k) * TLEN;
        ringR[k] = Rp[off];
        ringD[k] = Dp[off];
    }

    float pfE[4], pfQ[4];
    float Eprev = 0.0f, Qown = QNEG;     // own (i, j+1)
    float Ediag = 0.0f, Qdiag = QNEG;    // (i+1, j+1)
    float accS = 0.0f, accW = 0.0f;

    int t = -Gw;
    for (int s8 = 0; s8 < SMAX; s8 += 8) {
#pragma unroll
        for (int k = 0; k < 8; k++) {
            // 1. successors below via shuffle (lane 31: boundary consume)
            float Eup = __shfl_down_sync(0xFFFFFFFFu, Eprev, 1);
            float Qup = __shfl_down_sync(0xFFFFFFFFu, Qown, 1);
            if (l == 31) {
                float be = pfE[(s8 + k) & 3];
                float bq = pfQ[(s8 + k) & 3];
                bool use = (w < 7) && ((unsigned)(255 - t) <= 255u);
                Eup = use ? be : 0.0f;
                Qup = use ? bq : QNEG;
            }
            // 2. boundary prefetch 4 ahead
            if (l == 31 && w < 7) {
                int c = 251 - t;
                if ((unsigned)c <= 255u) {
                    pfE[(s8 + k) & 3] = ((volatile float*)bndE[w + 1])[c & 63];
                    pfQ[(s8 + k) & 3] = ((volatile float*)bndQ[w + 1])[c & 63];
                }
            }
            // 3. compute
            int j = 286 - t - l;
            if ((unsigned)j <= 255u) {
                float R  = ringR[(s8 + k) & 7];
                float Dv = ringD[(s8 + k) & 7];
                float Q  = (R - Dv) * KE2;
                float E;
                if (i == 255 && j == 255) {
                    E = 1.0f;                        // seed
                } else {
                    float tme = R * KE2;
                    E =          Eup   * ex2f_(Qup   - tme);
                    E = fmaf(Eprev, ex2f_(Qown  - tme), E);
                    E = fmaf(Ediag, ex2f_(Qdiag - tme), E);
                }
                accS += E;
                float dw = (float)(i - j);
                accW = fmaf(E, dw * dw, accW);
                if (l == 0) {
                    ((volatile float*)bndE[w])[j & 63] = E;
                    ((volatile float*)bndQ[w])[j & 63] = Q;
                }
                Ediag = Eup; Qdiag = Qup;
                Eprev = E;   Qown  = Q;
            }
            // 4. refill R/D rings
            if ((unsigned)(t + 8) <= 286u) {
                size_t off = (size_t)(rowtop - (t + 8)) * TLEN;
                ringR[(s8 + k) & 7] = Rp[off];
                ringD[(s8 + k) & 7] = Dp[off];
            }
            t++;
        }
        __syncthreads();
    }

    accW *= (1.0f / (255.0f * 255.0f));   // omega /(T-1)^2

#pragma unroll
    for (int off = 16; off; off >>= 1) {
        accS += __shfl_down_sync(0xFFFFFFFFu, accS, off);
        accW += __shfl_down_sync(0xFFFFFFFFu, accW, off);
    }
    if (l == 0) { red[w] = accS; red[w + 8] = accW; }
    __syncthreads();
    if (tid == 0) {
        float s = 0.0f, wv = 0.0f;
#pragma unroll
        for (int q = 0; q < 8; q++) { s += red[q]; wv += red[q + 8]; }
        g_den[b] = s;
        g_num[b] = wv;
    }
}

// ---------------------------------------------------------------------------
// Kernel 4: final scalar.
// ---------------------------------------------------------------------------
__global__ void final_kernel(float* __restrict__ out)
{
    __shared__ float red[4];
    const int t = threadIdx.x;   // 128 threads, one per batch

    float shape = g_shape[t] * (1.0f / 256.0f);
    float den   = g_den[t]   * (1.0f / 256.0f);
    float num   = g_num[t]   * (1.0f / 256.0f);
    float temporal = num / fmaxf(den, 1e-8f);
    float val = 0.5f * shape + 0.5f * temporal;

#pragma unroll
    for (int off = 16; off; off >>= 1)
        val += __shfl_down_sync(0xFFFFFFFFu, val, off);
    if ((t & 31) == 0) red[t >> 5] = val;
    __syncthreads();
    if (t == 0)
        out[0] = (red[0] + red[1] + red[2] + red[3]) * (1.0f / 128.0f);
}

// ---------------------------------------------------------------------------
extern "C" void kernel_launch(void* const* d_in, const int* in_sizes, int n_in,
                              void* d_out, int out_size)
{
    const float* preds   = (const float*)d_in[0];
    const float* targets = (const float*)d_in[1];

    dist_kernel<<<dim3(4, 4, BATCH), 256>>>(preds, targets);
    fwd_kernel<<<BATCH, 256>>>();
    bwd_kernel<<<BATCH, 256>>>();
    final_kernel<<<1, 128>>>((float*)d_out);
}

// round 7
// speedup vs baseline: 1.2138x; 1.2138x over previous
#include <cuda_runtime.h>

// ---------------------------------------------------------------------------
// DILATE loss. B=128, T=256, D=64, gamma=0.01, alpha=0.5, eps=1e-8, BIG=1e10.
// Wavefront kernels: 2 diagonals per barrier (halo-redundant), 4-phase register
// prefetch rings for ALL global streams including the halo lanes (no dependent
// global loads anywhere in the recurrence), single-instruction MUFU.
// ---------------------------------------------------------------------------

#define BATCH 128
#define TLEN  256
#define NDIAG 511            // 2*TLEN - 1
#define PAD   8              // diag padding each side (ring overshoot)
#define NDIAGT (NDIAG + 2 * PAD)
#define BIGV  1e10f
// exp(x/gamma) = exp2(x * KE2);  KE2 = (1/gamma)*log2(e)
#define KE2   144.26950408889634f
// gamma * ln(2)
#define KL    0.006931471805599453f

__device__ float g_D[(size_t)BATCH * NDIAGT * TLEN];
__device__ float g_R[(size_t)BATCH * NDIAGT * TLEN];
__device__ float g_shape[BATCH];
__device__ float g_num[BATCH];
__device__ float g_den[BATCH];

__device__ __forceinline__ size_t DI(int b, int d, int i) {
    return ((size_t)b * NDIAGT + (d + PAD)) * TLEN + i;
}

__device__ __forceinline__ float ex2f_(float x) {
    float y; asm("ex2.approx.ftz.f32 %0, %1;" : "=f"(y) : "f"(x)); return y;
}
__device__ __forceinline__ float lg2f_(float x) {
    float y; asm("lg2.approx.ftz.f32 %0, %1;" : "=f"(y) : "f"(x)); return y;
}
__device__ __forceinline__ float softmin3(float z0, float z1, float z2) {
    float m = fminf(z0, fminf(z1, z2));
    float s = ex2f_((m - z0) * KE2) + ex2f_((m - z1) * KE2)
            + ex2f_((m - z2) * KE2);
    return m - KL * lg2f_(s);
}

// ---------------------------------------------------------------------------
// Kernel 1: pairwise squared distances in diagonal layout (float4 smem).
// ---------------------------------------------------------------------------
__global__ __launch_bounds__(256) void dist_kernel(
    const float* __restrict__ preds, const float* __restrict__ targets)
{
    __shared__ float pool[2 * 64 * 68 + 128];
    float*  ps  = pool;                   // [64][68]
    float*  ts  = pool + 64 * 68;
    float*  pn  = pool + 2 * 64 * 68;     // [64]
    float*  tn  = pn + 64;
    float4* ps4 = (float4*)ps;            // pitch 17
    float4* ts4 = (float4*)ts;

    const int b  = blockIdx.z;
    const int i0 = blockIdx.y * 64;
    const int j0 = blockIdx.x * 64;
    const int tid = threadIdx.x;

    const float4* pb4 = (const float4*)(preds   + (size_t)b * TLEN * 64 + (size_t)i0 * 64);
    const float4* tb4 = (const float4*)(targets + (size_t)b * TLEN * 64 + (size_t)j0 * 64);

#pragma unroll
    for (int q = 0; q < 4; q++) {
        int idx = q * 256 + tid;          // 0..1023 float4s
        int r = idx >> 4, c4 = idx & 15;
        ps4[r * 17 + c4] = pb4[idx];
        ts4[r * 17 + c4] = tb4[idx];
    }
    __syncthreads();

    if (tid < 128) {
        const float* src = (tid < 64) ? ps : ts;
        float* dst = (tid < 64) ? pn : tn;
        int r = tid & 63;
        float s = 0.0f;
#pragma unroll
        for (int k = 0; k < 64; k++) { float v = src[r * 68 + k]; s = fmaf(v, v, s); }
        dst[r] = s;
    }
    __syncthreads();

    const int tx = tid & 15, ty = tid >> 4;
    const int ib = ty * 4, jb = tx * 4;

    float acc[4][4];
#pragma unroll
    for (int r = 0; r < 4; r++)
#pragma unroll
        for (int c = 0; c < 4; c++) acc[r][c] = 0.0f;

#pragma unroll 4
    for (int kq = 0; kq < 16; kq++) {
        float4 pv[4], tv[4];
#pragma unroll
        for (int r = 0; r < 4; r++) pv[r] = ps4[(ib + r) * 17 + kq];
#pragma unroll
        for (int c = 0; c < 4; c++) tv[c] = ts4[(jb + c) * 17 + kq];
#pragma unroll
        for (int r = 0; r < 4; r++)
#pragma unroll
            for (int c = 0; c < 4; c++) {
                acc[r][c] = fmaf(pv[r].x, tv[c].x, acc[r][c]);
                acc[r][c] = fmaf(pv[r].y, tv[c].y, acc[r][c]);
                acc[r][c] = fmaf(pv[r].z, tv[c].z, acc[r][c]);
                acc[r][c] = fmaf(pv[r].w, tv[c].w, acc[r][c]);
            }
    }

    float pnr[4], tnr[4];
#pragma unroll
    for (int r = 0; r < 4; r++) pnr[r] = pn[ib + r];
#pragma unroll
    for (int c = 0; c < 4; c++) tnr[c] = tn[jb + c];

    __syncthreads();

    // Stage tile diagonally: buf[tdd][ii], tdd = local i+j (0..126), pitch 65.
    float* buf = pool;
#pragma unroll
    for (int r = 0; r < 4; r++)
#pragma unroll
        for (int c = 0; c < 4; c++) {
            int ii = ib + r, jj = jb + c;
            float dv = pnr[r] + tnr[c] - 2.0f * acc[r][c];
            buf[(ii + jj) * 65 + ii] = fmaxf(dv, 0.0f);
        }
    __syncthreads();

    for (int base = 0; base < 128; base += 4) {
        int tdd = base + (tid >> 6);
        int ii  = tid & 63;
        if (tdd < 127) {
            int jj = tdd - ii;
            if (jj >= 0 && jj < 64)
                g_D[DI(b, i0 + j0 + tdd, i0 + ii)] = buf[tdd * 65 + ii];
        }
    }
}

// ---------------------------------------------------------------------------
// Kernel 2: soft-DTW forward. 2 diagonals per barrier (halo X = R[d][i-1]).
// Rings: rA/rB = D[d], D[d+1] at col i; rH = D[d] at col i-1 (halo). All
// refills address 8 diagonals ahead -> no dependent global loads in the chain.
// ---------------------------------------------------------------------------
__global__ __launch_bounds__(256) void fwd_kernel()
{
    __shared__ float sR[4][260];   // R[dd][k] at sR[dd&3][k+2]; [0..1] = BIG pad
    const int b = blockIdx.x;
    const int i = threadIdx.x;

    for (int q = i; q < 4 * 260; q += 256) ((float*)sR)[q] = BIGV;
    __syncthreads();

    const float* Dbase  = g_D + ((size_t)b * NDIAGT + PAD) * TLEN;
    const float* Dp     = Dbase + i;
    const float* DpH    = Dbase + i - 1;   // halo column (pad rows keep i=0 safe)
    float*       Rp     = g_R + ((size_t)b * NDIAGT + PAD) * TLEN + i;

    float rA[4], rB[4], rH[4];
#pragma unroll
    for (int k = 0; k < 4; k++) {
        rA[k] = Dp[(2 * k) * TLEN];
        rB[k] = Dp[(2 * k + 1) * TLEN];
        rH[k] = DpH[(2 * k) * TLEN];
    }

    auto fstep = [&](int p, int k) {
        const int d = 2 * p;
        float DY = rA[k], DZ = rB[k], DXv = rH[k];
        rA[k] = Dp[(d + 8) * TLEN];
        rB[k] = Dp[(d + 9) * TLEN];
        rH[k] = DpH[(d + 8) * TLEN];

        const float* rm1 = sR[(d + 3) & 3];  // diag d-1
        const float* rm2 = sR[(d + 2) & 3];  // diag d-2

        // X = R[d][i-1] (halo)
        bool vX = (i >= 1) && (i <= d + 1) && (d - i < 255);
        float x = softmin3(rm2[i], rm1[i], rm1[i + 1]) + DXv;
        if (d == 0) x = DXv;          // cell (0,0) when vX (i==1)
        if (!vX) x = BIGV;

        // Y = R[d][i]
        bool vY = (i <= d) && (d - i < 256);
        float z1y = rm1[i + 1];
        float y = softmin3(rm2[i + 1], z1y, rm1[i + 2]) + DY;
        if (d == 0 && i == 0) y = DY;
        if (!vY) y = BIGV;

        // Z = R[d+1][i]  (needs R[d-1][i-1]=z1y, X, Y)
        bool vZ = (i <= d + 1) && (d - i < 255);
        float z = softmin3(z1y, x, y) + DZ;
        if (!vZ) z = BIGV;

        Rp[(size_t)d * TLEN]       = y;
        Rp[(size_t)(d + 1) * TLEN] = z;
        sR[d & 3][i + 2]       = y;
        sR[(d + 1) & 3][i + 2] = z;
        __syncthreads();
    };

#pragma unroll 1
    for (int g = 0; g < 63; g++) {
#pragma unroll
        for (int k = 0; k < 4; k++) fstep(g * 4 + k, k);
    }
    fstep(252, 0); fstep(253, 1); fstep(254, 2);

    // Epilogue: diag 510.
    {
        const int d = 510;
        float DY = rA[3];
        const float* rm1 = sR[(d + 3) & 3];
        const float* rm2 = sR[(d + 2) & 3];
        float y = softmin3(rm2[i + 1], rm1[i + 1], rm1[i + 2]) + DY;
        if (i < 255) y = BIGV;
        Rp[(size_t)d * TLEN] = y;
        if (i == 255) g_shape[b] = y;   // R[255,255]
    }
}

// ---------------------------------------------------------------------------
// Kernel 3: soft-DTW gradient, reverse. 2 diagonals per barrier
// (halo X = E[d][i+1]).  Q = (R - D) * KE2.
// Rings: rR0/rD0 (diag d, col i), rR1/rD1 (diag d-1, col i),
//        rRx/rDx (diag d, col i+1 halo). No dependent global loads.
// ---------------------------------------------------------------------------
__global__ __launch_bounds__(256) void bwd_kernel()
{
    __shared__ float sE[4][260];   // position k at [k]; [256..259] = 0 pad
    __shared__ float sQ[4][260];
    __shared__ float red[16];

    const int b = blockIdx.x;
    const int i = threadIdx.x;

    for (int q = i; q < 4 * 260; q += 256) {
        ((float*)sE)[q] = 0.0f;
        ((float*)sQ)[q] = 0.0f;
    }
    __syncthreads();

    const float* Rbase = g_R + ((size_t)b * NDIAGT + PAD) * TLEN;
    const float* Dbase = g_D + ((size_t)b * NDIAGT + PAD) * TLEN;
    const float* Rp  = Rbase + i;
    const float* Dp  = Dbase + i;
    const float* RpX = Rbase + i + 1;   // halo column (pad rows keep i=255 safe)
    const float* DpX = Dbase + i + 1;

    float rR0[4], rD0[4], rR1[4], rD1[4], rRx[4], rDx[4];
#pragma unroll
    for (int k = 0; k < 4; k++) {
        rR0[k] = Rp[(size_t)(510 - 2 * k) * TLEN];
        rD0[k] = Dp[(size_t)(510 - 2 * k) * TLEN];
        rR1[k] = Rp[(size_t)(509 - 2 * k) * TLEN];
        rD1[k] = Dp[(size_t)(509 - 2 * k) * TLEN];
        rRx[k] = RpX[(size_t)(510 - 2 * k) * TLEN];
        rDx[k] = DpX[(size_t)(510 - 2 * k) * TLEN];
    }

    float accS = 0.0f, accW = 0.0f;

    auto bstep = [&](int p, int k) {
        const int d = 510 - 2 * p;
        float R0 = rR0[k], D0 = rD0[k], R1 = rR1[k], D1 = rD1[k];
        float Rx = rRx[k], Dx = rDx[k];
        rR0[k] = Rp[(size_t)(d - 8) * TLEN];
        rD0[k] = Dp[(size_t)(d - 8) * TLEN];
        rR1[k] = Rp[(size_t)(d - 9) * TLEN];
        rD1[k] = Dp[(size_t)(d - 9) * TLEN];
        rRx[k] = RpX[(size_t)(d - 8) * TLEN];
        rDx[k] = DpX[(size_t)(d - 8) * TLEN];

        const int j = d - i;
        const float* eN1 = sE[(d + 1) & 3]; const float* qN1 = sQ[(d + 1) & 3];
        const float* eN2 = sE[(d + 2) & 3]; const float* qN2 = sQ[(d + 2) & 3];

        // Y = E[d][i]
        bool vY = (i <= d) && (j < 256);
        float Y = 0.0f;
        if (vY) {
            float tY = R0 * KE2;
            float e = 0.0f;
            if (i < 255) e = fmaf(eN1[i + 1], ex2f_(qN1[i + 1] - tY), e);
            if (j < 255) e = fmaf(eN1[i],     ex2f_(qN1[i]     - tY), e);
            if (i < 255 && j < 255)
                         e = fmaf(eN2[i + 1], ex2f_(qN2[i + 1] - tY), e);
            Y = e;
        }
        if (d == 510) Y = (i == 255) ? 1.0f : 0.0f;

        // X = E[d][i+1] (halo)
        bool vX = (i < 255) && (i + 1 <= d) && (d - i - 1 < 256);
        float X = 0.0f;
        if (vX) {
            float tX = Rx * KE2;
            float e = 0.0f;
            if (i + 1 < 255) e = fmaf(eN1[i + 2], ex2f_(qN1[i + 2] - tX), e);
            if (j - 1 < 255) e = fmaf(eN1[i + 1], ex2f_(qN1[i + 1] - tX), e);
            if (i + 1 < 255 && j - 1 < 255)
                             e = fmaf(eN2[i + 2], ex2f_(qN2[i + 2] - tX), e);
            X = e;
        }
        if (d == 510) X = (i + 1 == 255) ? 1.0f : 0.0f;

        // Z = E[d-1][i]
        float QY = (R0 - D0) * KE2;
        float QX = (Rx - Dx) * KE2;
        bool vZ = (i <= d - 1) && (d - 1 - i < 256);
        float Z = 0.0f;
        if (vZ) {
            float tZ = R1 * KE2;
            float e = 0.0f;
            if (i < 255)         e = fmaf(X, ex2f_(QX - tZ), e);
            if (d - 1 - i < 255) e = fmaf(Y, ex2f_(QY - tZ), e);
            if (i < 255 && d - 1 - i < 255)
                                 e = fmaf(eN1[i + 1], ex2f_(qN1[i + 1] - tZ), e);
            Z = e;
        }

        if (vY) { accS += Y; float w = (float)(i - j);       accW = fmaf(Y, w * w, accW); }
        if (vZ) { accS += Z; float w = (float)(i - (j - 1)); accW = fmaf(Z, w * w, accW); }

        sE[d & 3][i] = Y;       sQ[d & 3][i] = QY;
        sE[(d - 1) & 3][i] = Z; sQ[(d - 1) & 3][i] = (R1 - D1) * KE2;
        __syncthreads();
    };

#pragma unroll 1
    for (int g = 0; g < 63; g++) {
#pragma unroll
        for (int k = 0; k < 4; k++) bstep(g * 4 + k, k);
    }
    bstep(252, 0); bstep(253, 1); bstep(254, 2);

    // Epilogue: diag 0 (cell (0,0); omega weight = 0).
    if (i == 0) {
        float tY = rR0[3] * KE2;
        float e = 0.0f;
        e = fmaf(sE[1][1], ex2f_(sQ[1][1] - tY), e);
        e = fmaf(sE[1][0], ex2f_(sQ[1][0] - tY), e);
        e = fmaf(sE[2][1], ex2f_(sQ[2][1] - tY), e);
        accS += e;
    }

    accW *= (1.0f / (255.0f * 255.0f));

#pragma unroll
    for (int off = 16; off; off >>= 1) {
        accS += __shfl_down_sync(0xFFFFFFFFu, accS, off);
        accW += __shfl_down_sync(0xFFFFFFFFu, accW, off);
    }
    const int w = i >> 5, l = i & 31;
    if (l == 0) { red[w] = accS; red[w + 8] = accW; }
    __syncthreads();
    if (i == 0) {
        float s = 0.0f, wv = 0.0f;
#pragma unroll
        for (int q = 0; q < 8; q++) { s += red[q]; wv += red[q + 8]; }
        g_den[b] = s;
        g_num[b] = wv;
    }
}

// ---------------------------------------------------------------------------
// Kernel 4: final scalar.
// ---------------------------------------------------------------------------
__global__ void final_kernel(float* __restrict__ out)
{
    __shared__ float red[4];
    const int t = threadIdx.x;   // 128 threads, one per batch

    float shape = g_shape[t] * (1.0f / 256.0f);
    float den   = g_den[t]   * (1.0f / 256.0f);
    float num   = g_num[t]   * (1.0f / 256.0f);
    float temporal = num / fmaxf(den, 1e-8f);
    float val = 0.5f * shape + 0.5f * temporal;

#pragma unroll
    for (int off = 16; off; off >>= 1)
        val += __shfl_down_sync(0xFFFFFFFFu, val, off);
    if ((t & 31) == 0) red[t >> 5] = val;
    __syncthreads();
    if (t == 0)
        out[0] = (red[0] + red[1] + red[2] + red[3]) * (1.0f / 128.0f);
}

// ---------------------------------------------------------------------------
extern "C" void kernel_launch(void* const* d_in, const int* in_sizes, int n_in,
                              void* d_out, int out_size)
{
    const float* preds   = (const float*)d_in[0];
    const float* targets = (const float*)d_in[1];

    dist_kernel<<<dim3(4, 4, BATCH), 256>>>(preds, targets);
    fwd_kernel<<<BATCH, 256>>>();
    bwd_kernel<<<BATCH, 256>>>();
    final_kernel<<<1, 128>>>((float*)d_out);
}